// round 2
// baseline (speedup 1.0000x reference)
#include <cuda_runtime.h>
#include <math.h>

#define B_ 256
#define S_ 120
#define T_ 24
#define D_ 216
#define H_ 1024
#define G_ 4096           // 4*H
#define KTOT (H_ + D_)    // 1240

// ---------------- scratch (device globals; no allocations allowed) ----------
__device__ float g_h[2][B_ * H_];     // ping-pong hidden state
__device__ float g_c[B_ * H_];        // cell state (in-place update)
__device__ float g_gates[B_ * G_];    // pre-activation gates for current step
__device__ float g_xdec[B_ * D_];     // decoder feedback input
__device__ float g_proj[8][B_ * D_];  // split-K partials for output projection

// ---------------- init ------------------------------------------------------
__global__ void init_kernel() {
    int idx = blockIdx.x * blockDim.x + threadIdx.x;
    if (idx < B_ * H_) { g_h[0][idx] = 0.f; g_c[idx] = 0.f; }
}

// ---------------- gates GEMM ------------------------------------------------
// g_gates[b][g] = sum_{k<1024} h[b][k]*W_hh[g][k] + sum_{k<216} x[b][k]*W_ih[g][k]
// Tile: BM=128, BN=64, BK=8. 256 threads, 8x4 microtile. Double-buffered smem.
// Grid: (4096/64, 256/128) = (64, 2) = 128 blocks.
__global__ void __launch_bounds__(256, 2)
gates_gemm(int hbuf, const float* __restrict__ xsrc, int xstride, int use_xdec,
           const float* __restrict__ Whh, const float* __restrict__ Wih)
{
    __shared__ float As[2][8][132];   // [buf][k][m], padded
    __shared__ float Bs[2][8][68];    // [buf][k][n], padded

    const float* __restrict__ h = g_h[hbuf];
    const float* __restrict__ x = use_xdec ? g_xdec : xsrc;
    if (use_xdec) xstride = D_;

    int tid = threadIdx.x;
    int m0  = blockIdx.y * 128;
    int n0  = blockIdx.x * 64;

    int lmA = tid >> 1;            // 0..127
    int lkA = (tid & 1) * 4;       // 0 or 4  (float4 along k)
    int lmB = tid >> 2;            // 0..63
    int lkB = (tid & 3) * 2;       // 0,2,4,6 (float2 along k)

    int ty = tid >> 4;             // 0..15 -> rows ty*8..ty*8+7
    int tx = tid & 15;             // 0..15 -> cols tx*4..tx*4+3

    float acc[8][4];
    #pragma unroll
    for (int i = 0; i < 8; i++)
        #pragma unroll
        for (int j = 0; j < 4; j++) acc[i][j] = 0.f;

    float4 aR;
    float2 bR;

    // prologue: load chunk 0 (always in the h / W_hh region)
    aR = *(const float4*)&h[(m0 + lmA) * H_ + lkA];
    bR = *(const float2*)&Whh[(n0 + lmB) * H_ + lkB];
    As[0][lkA + 0][lmA] = aR.x; As[0][lkA + 1][lmA] = aR.y;
    As[0][lkA + 2][lmA] = aR.z; As[0][lkA + 3][lmA] = aR.w;
    Bs[0][lkB + 0][lmB] = bR.x; Bs[0][lkB + 1][lmB] = bR.y;
    __syncthreads();

    const int NC = KTOT / 8;  // 155 chunks; chunks [0,128) are h, [128,155) are x
    for (int ch = 1; ch <= NC; ch++) {
        if (ch < NC) {
            int k0 = ch * 8;
            if (k0 < H_) {
                aR = *(const float4*)&h[(m0 + lmA) * H_ + k0 + lkA];
                bR = *(const float2*)&Whh[(n0 + lmB) * H_ + k0 + lkB];
            } else {
                int kk = k0 - H_;
                aR = *(const float4*)&x[(m0 + lmA) * xstride + kk + lkA];
                bR = *(const float2*)&Wih[(n0 + lmB) * D_ + kk + lkB];
            }
        }
        int cbuf = (ch - 1) & 1;
        #pragma unroll
        for (int k = 0; k < 8; k++) {
            float4 a0 = *(const float4*)&As[cbuf][k][ty * 8];
            float4 a1 = *(const float4*)&As[cbuf][k][ty * 8 + 4];
            float4 b  = *(const float4*)&Bs[cbuf][k][tx * 4];
            float av[8] = {a0.x, a0.y, a0.z, a0.w, a1.x, a1.y, a1.z, a1.w};
            float bv[4] = {b.x, b.y, b.z, b.w};
            #pragma unroll
            for (int i = 0; i < 8; i++)
                #pragma unroll
                for (int j = 0; j < 4; j++)
                    acc[i][j] += av[i] * bv[j];
        }
        if (ch < NC) {
            int sbuf = ch & 1;
            As[sbuf][lkA + 0][lmA] = aR.x; As[sbuf][lkA + 1][lmA] = aR.y;
            As[sbuf][lkA + 2][lmA] = aR.z; As[sbuf][lkA + 3][lmA] = aR.w;
            Bs[sbuf][lkB + 0][lmB] = bR.x; Bs[sbuf][lkB + 1][lmB] = bR.y;
        }
        __syncthreads();
    }

    #pragma unroll
    for (int i = 0; i < 8; i++) {
        float4 v = make_float4(acc[i][0], acc[i][1], acc[i][2], acc[i][3]);
        *(float4*)&g_gates[(m0 + ty * 8 + i) * G_ + n0 + tx * 4] = v;
    }
}

// ---------------- LSTM pointwise -------------------------------------------
__global__ void lstm_pointwise(int outbuf,
                               const float* __restrict__ b_ih,
                               const float* __restrict__ b_hh)
{
    int idx = blockIdx.x * blockDim.x + threadIdx.x;  // B_*H_ threads
    int b = idx >> 10;
    int j = idx & (H_ - 1);
    const float* gr = &g_gates[b * G_];
    float gi = gr[j]          + b_ih[j]          + b_hh[j];
    float gf = gr[H_ + j]     + b_ih[H_ + j]     + b_hh[H_ + j];
    float gg = gr[2 * H_ + j] + b_ih[2 * H_ + j] + b_hh[2 * H_ + j];
    float go = gr[3 * H_ + j] + b_ih[3 * H_ + j] + b_hh[3 * H_ + j];
    float si = 1.f / (1.f + expf(-gi));
    float sf = 1.f / (1.f + expf(-gf));
    float so = 1.f / (1.f + expf(-go));
    float c  = sf * g_c[idx] + si * tanhf(gg);
    g_c[idx] = c;
    g_h[outbuf][idx] = so * tanhf(c);
}

// ---------------- projection GEMM (split-K) ---------------------------------
// g_proj[ks][b][d] = sum_{k in slice ks} h[b][k] * W_out[d][k]
// Tile BM=128, BN=64, BK=8. Grid (ceil(216/64)=4, 2, splitK=8) = 64 blocks.
__global__ void __launch_bounds__(256, 2)
proj_gemm(int hbuf, const float* __restrict__ Wout)
{
    __shared__ float As[2][8][132];
    __shared__ float Bs[2][8][68];

    const float* __restrict__ h = g_h[hbuf];
    int tid = threadIdx.x;
    int n0 = blockIdx.x * 64;
    int m0 = blockIdx.y * 128;
    int ks = blockIdx.z;
    int kbase = ks * 128;

    int lmA = tid >> 1;
    int lkA = (tid & 1) * 4;
    int lmB = tid >> 2;
    int lkB = (tid & 3) * 2;
    int ty = tid >> 4;
    int tx = tid & 15;

    float acc[8][4];
    #pragma unroll
    for (int i = 0; i < 8; i++)
        #pragma unroll
        for (int j = 0; j < 4; j++) acc[i][j] = 0.f;

    float4 aR;
    float2 bR;
    int dB = n0 + lmB;

    aR = *(const float4*)&h[(m0 + lmA) * H_ + kbase + lkA];
    bR = (dB < D_) ? *(const float2*)&Wout[dB * H_ + kbase + lkB]
                   : make_float2(0.f, 0.f);
    As[0][lkA + 0][lmA] = aR.x; As[0][lkA + 1][lmA] = aR.y;
    As[0][lkA + 2][lmA] = aR.z; As[0][lkA + 3][lmA] = aR.w;
    Bs[0][lkB + 0][lmB] = bR.x; Bs[0][lkB + 1][lmB] = bR.y;
    __syncthreads();

    const int NC = 128 / 8;  // 16
    for (int ch = 1; ch <= NC; ch++) {
        if (ch < NC) {
            int k0 = kbase + ch * 8;
            aR = *(const float4*)&h[(m0 + lmA) * H_ + k0 + lkA];
            bR = (dB < D_) ? *(const float2*)&Wout[dB * H_ + k0 + lkB]
                           : make_float2(0.f, 0.f);
        }
        int cbuf = (ch - 1) & 1;
        #pragma unroll
        for (int k = 0; k < 8; k++) {
            float4 a0 = *(const float4*)&As[cbuf][k][ty * 8];
            float4 a1 = *(const float4*)&As[cbuf][k][ty * 8 + 4];
            float4 b  = *(const float4*)&Bs[cbuf][k][tx * 4];
            float av[8] = {a0.x, a0.y, a0.z, a0.w, a1.x, a1.y, a1.z, a1.w};
            float bv[4] = {b.x, b.y, b.z, b.w};
            #pragma unroll
            for (int i = 0; i < 8; i++)
                #pragma unroll
                for (int j = 0; j < 4; j++)
                    acc[i][j] += av[i] * bv[j];
        }
        if (ch < NC) {
            int sbuf = ch & 1;
            As[sbuf][lkA + 0][lmA] = aR.x; As[sbuf][lkA + 1][lmA] = aR.y;
            As[sbuf][lkA + 2][lmA] = aR.z; As[sbuf][lkA + 3][lmA] = aR.w;
            Bs[sbuf][lkB + 0][lmB] = bR.x; Bs[sbuf][lkB + 1][lmB] = bR.y;
        }
        __syncthreads();
    }

    #pragma unroll
    for (int i = 0; i < 8; i++)
        #pragma unroll
        for (int j = 0; j < 4; j++) {
            int col = n0 + tx * 4 + j;
            if (col < D_)
                g_proj[ks][(m0 + ty * 8 + i) * D_ + col] = acc[i][j];
        }
}

// ---------------- projection reduce + output write ---------------------------
__global__ void proj_reduce(const float* __restrict__ b_out,
                            float* __restrict__ out, int t)
{
    int idx = blockIdx.x * blockDim.x + threadIdx.x;
    if (idx >= B_ * D_) return;
    int b = idx / D_;
    int d = idx - b * D_;
    float v = b_out[d];
    #pragma unroll
    for (int s = 0; s < 8; s++) v += g_proj[s][idx];
    out[b * (T_ * D_) + t * D_ + d] = v;  // [B, T, D]
    g_xdec[idx] = v;                      // decoder feedback
}

// ---------------- host orchestration ----------------------------------------
extern "C" void kernel_launch(void* const* d_in, const int* in_sizes, int n_in,
                              void* d_out, int out_size)
{
    (void)in_sizes; (void)n_in; (void)out_size;
    const float* src   = (const float*)d_in[0];
    // d_in[1] = tgt: unused (eval-mode autoregressive decoder)
    const float* W_ih  = (const float*)d_in[2];
    const float* W_hh  = (const float*)d_in[3];
    const float* b_ih  = (const float*)d_in[4];
    const float* b_hh  = (const float*)d_in[5];
    const float* W_out = (const float*)d_in[6];
    const float* b_out = (const float*)d_in[7];
    // d_in[8] = max_len (== T_, compile-time)
    float* out = (float*)d_out;

    init_kernel<<<(B_ * H_ + 255) / 256, 256>>>();

    dim3 gg(G_ / 64, B_ / 128);   // (64, 2) = 128 blocks
    dim3 pg(4, B_ / 128, 8);      // (4, 2, 8) = 64 blocks
    int cur = 0;

    // Encoder: teacher-forced over src
    for (int t = 0; t < S_; t++) {
        gates_gemm<<<gg, 256>>>(cur, src + t * D_, S_ * D_, 0, W_hh, W_ih);
        lstm_pointwise<<<B_ * H_ / 256, 256>>>(1 - cur, b_ih, b_hh);
        cur ^= 1;
    }

    // Decoder: autoregressive from last src frame
    for (int t = 0; t < T_; t++) {
        if (t == 0)
            gates_gemm<<<gg, 256>>>(cur, src + (S_ - 1) * D_, S_ * D_, 0, W_hh, W_ih);
        else
            gates_gemm<<<gg, 256>>>(cur, src, 0, 1, W_hh, W_ih);
        lstm_pointwise<<<B_ * H_ / 256, 256>>>(1 - cur, b_ih, b_hh);
        cur ^= 1;
        proj_gemm<<<pg, 256>>>(cur, W_out);
        proj_reduce<<<(B_ * D_ + 255) / 256, 256>>>(b_out, out, t);
    }
}